// round 13
// baseline (speedup 1.0000x reference)
#include <cuda_runtime.h>
#include <math.h>
#include <stdint.h>

// ---------------------------------------------------------------------------
// MoEGate hybrid: bf16 tensor-core GEMM for *candidate ranking* + exact fp32
// re-rank of the top-12 candidates per token.  Selection / weights / counts
// come from exact fp32 logits (k-ascending fmaf — bitwise identical to the
// R2 all-fp32 kernel that passed at rel_err 9e-8), so correctness does not
// depend on tensor-core numerics at all.
//   X: [N=32768, 2048] f32   W: [64, 2048] f32
//   out f32: [ idx (N*8 as float) | weight (N*8) | aux (1) ]
// ---------------------------------------------------------------------------

#define DIM      2048
#define EXPERTS  64
#define TOPK     8
#define NCAND    12
#define MT       128
#define KC       32
#define KP       40            // X smem row stride (floats)
#define NTHREADS 256
#define BSZ      4
#define NCHUNK   (DIM / KC)    // 64 stages

// phase-1 buffers
#define XS_BYTES 20480
#define BUF_SZ   32768
#define SMEM_DYN 65536
// epilogue / phase-2 layout (bytes)
#define CNT_OFF  33280         // 64 ints (after scores[128][65])
#define RED_OFF  33536         // 256 floats
#define CAND_OFF 34560         // 128*12 ints
#define ACC_OFF  40704         // 128*12 floats   (ends 46848)
#define P2_W_OFF 20480         // phase-2 W tile [64][36] floats (9216 B)
#define P2_WP    36

__device__ uint2 g_w3[3 * 128 * 256];
__device__ float g_score_partial[256 * EXPERTS];
__device__ int   g_count_partial[256 * EXPERTS];
__device__ int   g_arrive = 0;

// ---- exact 3-way bf16 split -------------------------------------------------
__device__ __forceinline__ void split3(float v, uint32_t& h, uint32_t& m, uint32_t& l) {
    h = __float_as_uint(v) & 0xFFFF0000u;
    float r1 = v - __uint_as_float(h);
    m = __float_as_uint(r1) & 0xFFFF0000u;
    float r2 = r1 - __uint_as_float(m);
    l = __float_as_uint(r2);
}
__device__ __forceinline__ void split_pack(float va, float vb,
                                           uint32_t& hp, uint32_t& mp, uint32_t& lp) {
    uint32_t ha, ma, la, hb, mb, lb;
    split3(va, ha, ma, la);
    split3(vb, hb, mb, lb);
    hp = __byte_perm(ha, hb, 0x7632);
    mp = __byte_perm(ma, mb, 0x7632);
    lp = __byte_perm(la, lb, 0x7632);
}
__device__ __forceinline__ void mma_bf16(float* c, const uint32_t* a,
                                         uint32_t b0, uint32_t b1) {
    asm volatile(
        "mma.sync.aligned.m16n8k16.row.col.f32.bf16.bf16.f32 "
        "{%0,%1,%2,%3}, {%4,%5,%6,%7}, {%8,%9}, {%0,%1,%2,%3};"
        : "+f"(c[0]), "+f"(c[1]), "+f"(c[2]), "+f"(c[3])
        : "r"(a[0]), "r"(a[1]), "r"(a[2]), "r"(a[3]), "r"(b0), "r"(b1));
}

// ---------------------------------------------------------------------------
__global__ void mg_wsplit(const float* __restrict__ W)
{
    const int i  = blockIdx.x * 256 + threadIdx.x;
    const int t  = i & 3;
    const int n  = (i >> 2) & 63;
    const int kb = i >> 8;
    const float* wr = W + n * DIM + kb * 16 + t * 2;
    const float2 e0 = *reinterpret_cast<const float2*>(wr);
    const float2 e1 = *reinterpret_cast<const float2*>(wr + 8);
    uint32_t h0, m0, l0, h1, m1, l1;
    split_pack(e0.x, e0.y, h0, m0, l0);
    split_pack(e1.x, e1.y, h1, m1, l1);
    const int u = kb * 256 + n * 4 + t;
    g_w3[u]         = make_uint2(h0, h1);
    g_w3[32768 + u] = make_uint2(m0, m1);
    g_w3[65536 + u] = make_uint2(l0, l1);
}

// ---------------------------------------------------------------------------
extern __shared__ char dsm[];

__global__ __launch_bounds__(NTHREADS, 2)
void mg_fused(const float* __restrict__ X,
              const float* __restrict__ W,
              float* __restrict__ out,
              int n_tokens)
{
    const int tid = threadIdx.x;
    const int wid = tid >> 5, lid = tid & 31;
    const int tok0 = blockIdx.x * MT;

    const int warpM = wid >> 1;
    const int warpN = wid & 1;
    const int g   = lid >> 2;
    const int tg4 = lid & 3;

    const int c4 = tid & 7;
    const int r0 = tid >> 3;
    const float4* Xg = ((const float4*)X) + (size_t)(tok0 + r0) * (DIM / 4) + c4;
    const uint4*  Wg = reinterpret_cast<const uint4*>(g_w3);

    float acc[2][4][4];
#pragma unroll
    for (int m = 0; m < 2; m++)
#pragma unroll
        for (int n = 0; n < 4; n++)
#pragma unroll
            for (int r = 0; r < 4; r++) acc[m][n][r] = 0.0f;

    float* xs[2] = { (float*)dsm,              (float*)(dsm + BUF_SZ) };
    uint2* ws[2] = { (uint2*)(dsm + XS_BYTES), (uint2*)(dsm + BUF_SZ + XS_BYTES) };

    // ==== PHASE 1: bf16 6-term GEMM =========================================
    {
        float4 rx[4];
        uint4  rwq[3];
#pragma unroll
        for (int i = 0; i < 4; i++) rx[i] = Xg[(size_t)i * 32 * (DIM / 4)];
#pragma unroll
        for (int p = 0; p < 3; p++) rwq[p] = Wg[p * 16384 + tid];
#pragma unroll
        for (int i = 0; i < 4; i++)
            *(float4*)(xs[0] + (r0 + 32 * i) * KP + c4 * 4) = rx[i];
#pragma unroll
        for (int p = 0; p < 3; p++)
            *(uint4*)((char*)ws[0] + p * 4096 + tid * 16) = rwq[p];
    }
    __syncthreads();

    for (int c = 0; c < NCHUNK; c++) {
        const int cur = c & 1;
        float4 rx[4];
        uint4  rwq[3];
        if (c + 1 < NCHUNK) {
            const int k4 = (c + 1) * (KC / 4);
#pragma unroll
            for (int i = 0; i < 4; i++) rx[i] = Xg[(size_t)i * 32 * (DIM / 4) + k4];
#pragma unroll
            for (int p = 0; p < 3; p++)
                rwq[p] = Wg[p * 16384 + (c + 1) * 256 + tid];
        }

        const float* xb = xs[cur] + (warpM * 32 + g) * KP;
        const uint2* wb = ws[cur];

#pragma unroll
        for (int kbl = 0; kbl < 2; kbl++) {
            const int k0 = kbl * 16 + tg4 * 2;
            uint32_t Ah[2][4], Am[2][4], Al[2][4];
#pragma unroll
            for (int m = 0; m < 2; m++) {
                const float* rb  = xb + m * 16 * KP;
                const float* rb8 = rb + 8 * KP;
                const float2 p0 = *(const float2*)(rb  + k0);
                const float2 p1 = *(const float2*)(rb8 + k0);
                const float2 p2 = *(const float2*)(rb  + k0 + 8);
                const float2 p3 = *(const float2*)(rb8 + k0 + 8);
                split_pack(p0.x, p0.y, Ah[m][0], Am[m][0], Al[m][0]);
                split_pack(p1.x, p1.y, Ah[m][1], Am[m][1], Al[m][1]);
                split_pack(p2.x, p2.y, Ah[m][2], Am[m][2], Al[m][2]);
                split_pack(p3.x, p3.y, Ah[m][3], Am[m][3], Al[m][3]);
            }
#pragma unroll
            for (int nt = 0; nt < 4; nt++) {
                const int n = warpN * 32 + nt * 8 + g;
                const uint2 bh = wb[(0 * 2 + kbl) * 256 + n * 4 + tg4];
                const uint2 bm = wb[(1 * 2 + kbl) * 256 + n * 4 + tg4];
                const uint2 bl = wb[(2 * 2 + kbl) * 256 + n * 4 + tg4];
#pragma unroll
                for (int m = 0; m < 2; m++) {
                    float* ca = acc[m][nt];
                    mma_bf16(ca, Ah[m], bh.x, bh.y);
                    mma_bf16(ca, Am[m], bh.x, bh.y);
                    mma_bf16(ca, Ah[m], bm.x, bm.y);
                    mma_bf16(ca, Am[m], bm.x, bm.y);
                    mma_bf16(ca, Al[m], bh.x, bh.y);
                    mma_bf16(ca, Ah[m], bl.x, bl.y);
                }
            }
        }

        if (c + 1 < NCHUNK) {
            const int nxt = cur ^ 1;
#pragma unroll
            for (int i = 0; i < 4; i++)
                *(float4*)(xs[nxt] + (r0 + 32 * i) * KP + c4 * 4) = rx[i];
#pragma unroll
            for (int p = 0; p < 3; p++)
                *(uint4*)((char*)ws[nxt] + p * 4096 + tid * 16) = rwq[p];
        }
        __syncthreads();
    }

    // ==== EPILOGUE A: TC scores -> softmax -> aux partials -> top-12 ========
    float* scores = (float*)dsm;                  // [128][65]
    int*   cnt    = (int*)(dsm + CNT_OFF);
    float* red    = (float*)(dsm + RED_OFF);
    int*   candS  = (int*)(dsm + CAND_OFF);       // [128][12]
    float* eaccS  = (float*)(dsm + ACC_OFF);      // [128][12]

#pragma unroll
    for (int m = 0; m < 2; m++)
#pragma unroll
        for (int nt = 0; nt < 4; nt++) {
            const int r  = warpM * 32 + m * 16 + g;
            const int cb = warpN * 32 + nt * 8 + tg4 * 2;
            scores[r * 65 + cb]           = acc[m][nt][0];
            scores[r * 65 + cb + 1]       = acc[m][nt][1];
            scores[(r + 8) * 65 + cb]     = acc[m][nt][2];
            scores[(r + 8) * 65 + cb + 1] = acc[m][nt][3];
        }
    if (tid < EXPERTS) cnt[tid] = 0;
    __syncthreads();

    if (tid < MT) {                               // softmax (TC-approx)
        float* row = scores + tid * 65;
        float mx = -INFINITY;
#pragma unroll 8
        for (int e = 0; e < EXPERTS; e++) mx = fmaxf(mx, row[e]);
        float s = 0.0f;
#pragma unroll 8
        for (int e = 0; e < EXPERTS; e++) {
            const float p = expf(row[e] - mx);
            s += p;
            row[e] = p;
        }
        const float inv = 1.0f / s;
#pragma unroll 8
        for (int e = 0; e < EXPERTS; e++) row[e] *= inv;
    }
    __syncthreads();

    if (tid < EXPERTS) {                          // aux: per-expert score sums
        float s = 0.0f;
#pragma unroll 8
        for (int t = 0; t < MT; t++) s += scores[t * 65 + tid];
        g_score_partial[blockIdx.x * EXPERTS + tid] = s;
    }
    __syncthreads();

    if (tid < MT) {                               // top-12 candidates (approx)
        float* row = scores + tid * 65;
#pragma unroll
        for (int r = 0; r < NCAND; r++) {
            float best = -1.0f;
            int   bi = 0;
#pragma unroll 8
            for (int e = 0; e < EXPERTS; e++) {
                const float v = row[e];
                if (v > best) { best = v; bi = e; }
            }
            candS[tid * NCAND + r] = bi;
            row[bi] = -2.0f;
        }
    }
    __syncthreads();

    // ==== PHASE 2: exact fp32 recompute of 12 candidate logits ==============
    const int tk   = tid >> 1;                    // token
    const int half = tid & 1;                     // 0/1 -> candidates 0-5 / 6-11
    int cand[6];
#pragma unroll
    for (int j = 0; j < 6; j++) cand[j] = candS[tk * NCAND + half * 6 + j];
    float ea[6] = {0.f, 0.f, 0.f, 0.f, 0.f, 0.f};

    float* xt = (float*)dsm;                      // [128][40]  (scores now dead)
    float* wt = (float*)(dsm + P2_W_OFF);         // [64][36]
    const int wrow = tid >> 2, wq = tid & 3;
    const float4* W4 = ((const float4*)W) + (size_t)wrow * (DIM / 4) + wq * 2;

    {   // prologue: chunk 0
        float4 rx[4], w0, w1;
#pragma unroll
        for (int i = 0; i < 4; i++) rx[i] = Xg[(size_t)i * 32 * (DIM / 4)];
        w0 = W4[0]; w1 = W4[1];
#pragma unroll
        for (int i = 0; i < 4; i++)
            *(float4*)(xt + (r0 + 32 * i) * KP + c4 * 4) = rx[i];
        *(float4*)(wt + wrow * P2_WP + wq * 8)     = w0;
        *(float4*)(wt + wrow * P2_WP + wq * 8 + 4) = w1;
    }
    __syncthreads();

    for (int c = 0; c < NCHUNK; c++) {
        float4 rx[4], w0, w1;
        if (c + 1 < NCHUNK) {
            const int k4 = (c + 1) * (KC / 4);
#pragma unroll
            for (int i = 0; i < 4; i++) rx[i] = Xg[(size_t)i * 32 * (DIM / 4) + k4];
            w0 = W4[(c + 1) * 8];
            w1 = W4[(c + 1) * 8 + 1];
        }

        const float* xrow = xt + tk * KP;
#pragma unroll
        for (int kb2 = 0; kb2 < 4; kb2++) {
            const float4 xa = *(const float4*)(xrow + kb2 * 8);
            const float4 xb2 = *(const float4*)(xrow + kb2 * 8 + 4);
#pragma unroll
            for (int j = 0; j < 6; j++) {
                const float* wr = wt + cand[j] * P2_WP + kb2 * 8;
                const float4 wa = *(const float4*)(wr);
                const float4 wb2 = *(const float4*)(wr + 4);
                ea[j] = fmaf(xa.x, wa.x, ea[j]);
                ea[j] = fmaf(xa.y, wa.y, ea[j]);
                ea[j] = fmaf(xa.z, wa.z, ea[j]);
                ea[j] = fmaf(xa.w, wa.w, ea[j]);
                ea[j] = fmaf(xb2.x, wb2.x, ea[j]);
                ea[j] = fmaf(xb2.y, wb2.y, ea[j]);
                ea[j] = fmaf(xb2.z, wb2.z, ea[j]);
                ea[j] = fmaf(xb2.w, wb2.w, ea[j]);
            }
        }
        __syncthreads();
        if (c + 1 < NCHUNK) {
#pragma unroll
            for (int i = 0; i < 4; i++)
                *(float4*)(xt + (r0 + 32 * i) * KP + c4 * 4) = rx[i];
            *(float4*)(wt + wrow * P2_WP + wq * 8)     = w0;
            *(float4*)(wt + wrow * P2_WP + wq * 8 + 4) = w1;
            __syncthreads();
        }
    }

#pragma unroll
    for (int j = 0; j < 6; j++) eaccS[tk * NCAND + half * 6 + j] = ea[j];
    __syncthreads();

    // ==== EPILOGUE B: exact top-8, weights, counts ==========================
    if (tid < MT) {
        float lv[NCAND]; int le[NCAND];
#pragma unroll
        for (int j = 0; j < NCAND; j++) {
            lv[j] = eaccS[tid * NCAND + j];
            le[j] = candS[tid * NCAND + j];
        }
        float wsel[TOPK]; int isel[TOPK];
#pragma unroll
        for (int r = 0; r < TOPK; r++) {
            float best = -INFINITY; int bj = 0;
#pragma unroll
            for (int j = 0; j < NCAND; j++) {
                const float v = lv[j];
                const int   e = le[j];
                if (v > best || (v == best && e < le[bj])) { best = v; bj = j; }
            }
            wsel[r] = best; isel[r] = le[bj];
            lv[bj] = -INFINITY;
        }
        const float mx = wsel[0];
        float es[TOPK], ssum = 0.0f;
#pragma unroll
        for (int r = 0; r < TOPK; r++) { es[r] = expf(wsel[r] - mx); ssum += es[r]; }
        const float inv = 1.0f / ssum;
        const int tokG = tok0 + tid;
        float* out_idx = out + (size_t)tokG * TOPK;
        float* out_w   = out + (size_t)n_tokens * TOPK + (size_t)tokG * TOPK;
#pragma unroll
        for (int r = 0; r < TOPK; r++) {
            out_idx[r] = (float)isel[r];
            out_w[r]   = es[r] * inv;
            atomicAdd(&cnt[isel[r]], 1);
        }
    }
    __syncthreads();
    if (tid < EXPERTS)
        g_count_partial[blockIdx.x * EXPERTS + tid] = cnt[tid];

    // ==== aux loss: last CTA reduces ========================================
    __threadfence();
    __shared__ int lastFlag;
    if (tid == 0) {
        const int v = atomicAdd(&g_arrive, 1);
        lastFlag = (v == (int)gridDim.x - 1);
    }
    __syncthreads();
    if (lastFlag) {
        __threadfence();
        const int cpb = (int)gridDim.x / BSZ;
        const int b = tid >> 6, e = tid & 63;
        float s = 0.0f; int c = 0;
#pragma unroll 8
        for (int i = 0; i < 64; i++) {
            const int row = (b * cpb + i) * EXPERTS + e;
            s += g_score_partial[row];
            c += g_count_partial[row];
        }
        const int   seq  = n_tokens / BSZ;
        const float mean = s / (float)seq;
        const float ce   = (float)c * ((float)EXPERTS / (float)(seq * TOPK));
        red[tid] = ce * mean;
        __syncthreads();
        for (int st = 128; st > 0; st >>= 1) {
            if (tid < st) red[tid] += red[tid + st];
            __syncthreads();
        }
        if (tid == 0) {
            out[(size_t)n_tokens * 2 * TOPK] = red[0] * (0.1f / (float)BSZ);
            g_arrive = 0;
        }
    }
}

// ---------------------------------------------------------------------------
extern "C" void kernel_launch(void* const* d_in, const int* in_sizes, int n_in,
                              void* d_out, int out_size)
{
    const float* X = (const float*)d_in[0];
    const float* W = (const float*)d_in[1];
    float* out = (float*)d_out;

    const int n_tokens = in_sizes[0] / DIM;   // 32768
    const int n_cta    = n_tokens / MT;       // 256

    mg_wsplit<<<128, 256>>>(W);

    cudaFuncSetAttribute(mg_fused,
                         cudaFuncAttributeMaxDynamicSharedMemorySize, SMEM_DYN);
    mg_fused<<<n_cta, NTHREADS, SMEM_DYN>>>(X, W, out, n_tokens);
}

// round 16
// speedup vs baseline: 1.1642x; 1.1642x over previous
#include <cuda_runtime.h>
#include <math.h>
#include <stdint.h>

// ---------------------------------------------------------------------------
// MoEGate: pure fp32 GEMM using packed fma.rn.f32x2 (FFMA2, 2x fp32 rate on
// Blackwell) + fused softmax/top-8/renorm/aux.  Logit accumulation order is
// bitwise identical to the R2 kernel that passed at rel_err 9e-8 — selection
// never touches tensor-core numerics (every TC-selected variant failed with
// deterministic index flips).
//   X: [N=32768, 2048] f32   W: [64, 2048] f32
//   out f32: [ idx (N*8 as float) | weight (N*8) | aux (1) ]
// R15 fix: lastFlag folded into the smem union (static smem was 48KB + 4B).
// ---------------------------------------------------------------------------

#define DIM      2048
#define EXPERTS  64
#define TOPK     8
#define MT       128     // tokens per CTA
#define KC       32      // k-chunk
#define NTHREADS 256
#define BSZ      4
#define NCHUNK   (DIM / KC)   // 64

__device__ float g_score_partial[256 * EXPERTS];
__device__ int   g_count_partial[256 * EXPERTS];
__device__ int   g_arrive = 0;

__device__ __forceinline__ uint64_t pack_dup(float v) {
    uint64_t r;
    asm("mov.b64 %0, {%1, %1};" : "=l"(r) : "r"(__float_as_uint(v)));
    return r;
}
__device__ __forceinline__ void unpack2(uint64_t v, float& lo, float& hi) {
    uint32_t a, b;
    asm("mov.b64 {%0, %1}, %2;" : "=r"(a), "=r"(b) : "l"(v));
    lo = __uint_as_float(a);
    hi = __uint_as_float(b);
}
__device__ __forceinline__ void fma2(uint64_t& acc, uint64_t a, uint64_t b) {
    asm("fma.rn.f32x2 %0, %1, %2, %0;" : "+l"(acc) : "l"(a), "l"(b));
}

__global__ __launch_bounds__(NTHREADS, 2)
void mg_f32x2(const float* __restrict__ X,
              const float* __restrict__ W,
              float* __restrict__ out,
              int n_tokens)
{
    __shared__ union {
        struct {                       // GEMM phase (exactly 48 KB)
            float xs[2][KC][MT];       // x tile, transposed: [k][token]
            float ws[2][KC][EXPERTS];  // w tile, transposed: [k][expert]
        } gm;
        struct {                       // epilogue phase (aliases gm; 34564 B)
            float scores[MT][EXPERTS + 1];
            int   cnt[EXPERTS];
            float red[256];
            int   lastFlag;
        } ep;
    } sm;

    const int tid  = threadIdx.x;
    const int tg   = tid & 15;         // token group: tokens tg*8 .. tg*8+7
    const int eg   = tid >> 4;         // expert group: experts eg*4 .. eg*4+3
    const int tok0 = blockIdx.x * MT;

    // acc2[p][j]: packed pair of tokens (tg*8+2p, tg*8+2p+1), expert eg*4+j
    uint64_t acc2[4][4];
#pragma unroll
    for (int p = 0; p < 4; p++)
#pragma unroll
        for (int j = 0; j < 4; j++) acc2[p][j] = 0ull;

    const float4* __restrict__ X4 = reinterpret_cast<const float4*>(X);
    const float4* __restrict__ W4 = reinterpret_cast<const float4*>(W);

    const int lrow = tid >> 3;   // 0..31
    const int lkq  = tid & 7;    // 0..7

    float4 rx[4], rw[2];

    // ---- prologue: chunk 0 into buffer 0 ----------------------------------
    {
#pragma unroll
        for (int i = 0; i < 4; i++)
            rx[i] = X4[(size_t)(tok0 + lrow + i * 32) * (DIM / 4) + lkq];
#pragma unroll
        for (int i = 0; i < 2; i++)
            rw[i] = W4[(size_t)(lrow + i * 32) * (DIM / 4) + lkq];
#pragma unroll
        for (int i = 0; i < 4; i++) {
            const int t = lrow + i * 32;
            sm.gm.xs[0][lkq * 4 + 0][t] = rx[i].x;
            sm.gm.xs[0][lkq * 4 + 1][t] = rx[i].y;
            sm.gm.xs[0][lkq * 4 + 2][t] = rx[i].z;
            sm.gm.xs[0][lkq * 4 + 3][t] = rx[i].w;
        }
#pragma unroll
        for (int i = 0; i < 2; i++) {
            const int e = lrow + i * 32;
            sm.gm.ws[0][lkq * 4 + 0][e] = rw[i].x;
            sm.gm.ws[0][lkq * 4 + 1][e] = rw[i].y;
            sm.gm.ws[0][lkq * 4 + 2][e] = rw[i].z;
            sm.gm.ws[0][lkq * 4 + 3][e] = rw[i].w;
        }
    }
    __syncthreads();

    // ---- main loop: LDG(next) | FMA2(cur) | STS(next) | sync ---------------
    for (int c = 0; c < NCHUNK; c++) {
        const int cur = c & 1;
        const int nxt = cur ^ 1;

        if (c + 1 < NCHUNK) {
            const int k4 = (c + 1) * (KC / 4);
#pragma unroll
            for (int i = 0; i < 4; i++)
                rx[i] = X4[(size_t)(tok0 + lrow + i * 32) * (DIM / 4) + k4 + lkq];
#pragma unroll
            for (int i = 0; i < 2; i++)
                rw[i] = W4[(size_t)(lrow + i * 32) * (DIM / 4) + k4 + lkq];
        }

        const float* xsk = &sm.gm.xs[cur][0][0];
        const float* wsk = &sm.gm.ws[cur][0][0];
#pragma unroll 8
        for (int kk = 0; kk < KC; kk++) {
            // token pairs: direct LDS.64 of adjacent tokens (zero pack cost)
            const uint64_t* xp =
                reinterpret_cast<const uint64_t*>(xsk + kk * MT + tg * 8);
            const uint64_t xq0 = xp[0];
            const uint64_t xq1 = xp[1];
            const uint64_t xq2 = xp[2];
            const uint64_t xq3 = xp[3];
            const float4 w =
                *reinterpret_cast<const float4*>(wsk + kk * EXPERTS + eg * 4);
            const uint64_t wq0 = pack_dup(w.x);
            const uint64_t wq1 = pack_dup(w.y);
            const uint64_t wq2 = pack_dup(w.z);
            const uint64_t wq3 = pack_dup(w.w);

            fma2(acc2[0][0], xq0, wq0); fma2(acc2[0][1], xq0, wq1);
            fma2(acc2[0][2], xq0, wq2); fma2(acc2[0][3], xq0, wq3);
            fma2(acc2[1][0], xq1, wq0); fma2(acc2[1][1], xq1, wq1);
            fma2(acc2[1][2], xq1, wq2); fma2(acc2[1][3], xq1, wq3);
            fma2(acc2[2][0], xq2, wq0); fma2(acc2[2][1], xq2, wq1);
            fma2(acc2[2][2], xq2, wq2); fma2(acc2[2][3], xq2, wq3);
            fma2(acc2[3][0], xq3, wq0); fma2(acc2[3][1], xq3, wq1);
            fma2(acc2[3][2], xq3, wq2); fma2(acc2[3][3], xq3, wq3);
        }

        if (c + 1 < NCHUNK) {
#pragma unroll
            for (int i = 0; i < 4; i++) {
                const int t = lrow + i * 32;
                sm.gm.xs[nxt][lkq * 4 + 0][t] = rx[i].x;
                sm.gm.xs[nxt][lkq * 4 + 1][t] = rx[i].y;
                sm.gm.xs[nxt][lkq * 4 + 2][t] = rx[i].z;
                sm.gm.xs[nxt][lkq * 4 + 3][t] = rx[i].w;
            }
#pragma unroll
            for (int i = 0; i < 2; i++) {
                const int e = lrow + i * 32;
                sm.gm.ws[nxt][lkq * 4 + 0][e] = rw[i].x;
                sm.gm.ws[nxt][lkq * 4 + 1][e] = rw[i].y;
                sm.gm.ws[nxt][lkq * 4 + 2][e] = rw[i].z;
                sm.gm.ws[nxt][lkq * 4 + 3][e] = rw[i].w;
            }
        }
        __syncthreads();
    }

    // ---- epilogue: logits -> smem (re-using GEMM smem) ---------------------
#pragma unroll
    for (int p = 0; p < 4; p++)
#pragma unroll
        for (int j = 0; j < 4; j++) {
            float lo, hi;
            unpack2(acc2[p][j], lo, hi);
            sm.ep.scores[tg * 8 + 2 * p][eg * 4 + j]     = lo;
            sm.ep.scores[tg * 8 + 2 * p + 1][eg * 4 + j] = hi;
        }
    if (tid < EXPERTS) sm.ep.cnt[tid] = 0;
    __syncthreads();

    // softmax per token
    if (tid < MT) {
        float* row = sm.ep.scores[tid];
        float m = -INFINITY;
#pragma unroll 8
        for (int e = 0; e < EXPERTS; e++) m = fmaxf(m, row[e]);
        float s = 0.0f;
#pragma unroll 8
        for (int e = 0; e < EXPERTS; e++) {
            const float p = expf(row[e] - m);
            s += p;
            row[e] = p;
        }
        const float inv = 1.0f / s;
#pragma unroll 8
        for (int e = 0; e < EXPERTS; e++) row[e] *= inv;
    }
    __syncthreads();

    // per-expert score sums over this CTA's tokens (deterministic)
    if (tid < EXPERTS) {
        float s = 0.0f;
#pragma unroll 8
        for (int t = 0; t < MT; t++) s += sm.ep.scores[t][tid];
        g_score_partial[blockIdx.x * EXPERTS + tid] = s;
    }
    __syncthreads();

    // top-8: strict '>' argmax == jax.lax.top_k stable descending
    if (tid < MT) {
        float* row = sm.ep.scores[tid];
        float wsel[TOPK];
        int   isel[TOPK];
        float ssum = 0.0f;
#pragma unroll
        for (int r = 0; r < TOPK; r++) {
            float best = -1.0f;
            int   bi   = 0;
#pragma unroll 8
            for (int e = 0; e < EXPERTS; e++) {
                const float v = row[e];
                if (v > best) { best = v; bi = e; }
            }
            wsel[r] = best;
            isel[r] = bi;
            ssum   += best;
            row[bi] = -2.0f;
            atomicAdd(&sm.ep.cnt[bi], 1);
        }
        const float invw = 1.0f / (ssum + 1e-20f);
        const int tokG = tok0 + tid;
        float* out_idx = out + (size_t)tokG * TOPK;
        float* out_w   = out + (size_t)n_tokens * TOPK + (size_t)tokG * TOPK;
#pragma unroll
        for (int r = 0; r < TOPK; r++) {
            out_idx[r] = (float)isel[r];
            out_w[r]   = wsel[r] * invw;
        }
    }
    __syncthreads();
    if (tid < EXPERTS)
        g_count_partial[blockIdx.x * EXPERTS + tid] = sm.ep.cnt[tid];

    // ---- aux loss: last CTA reduces (fixed order, deterministic) -----------
    __threadfence();
    if (tid == 0) {
        const int v = atomicAdd(&g_arrive, 1);
        sm.ep.lastFlag = (v == (int)gridDim.x - 1);
    }
    __syncthreads();
    if (sm.ep.lastFlag) {
        __threadfence();
        const int cpb = (int)gridDim.x / BSZ;   // 64
        const int b = tid >> 6, e = tid & 63;
        float s = 0.0f; int c = 0;
#pragma unroll 8
        for (int i = 0; i < 64; i++) {
            const int row = (b * cpb + i) * EXPERTS + e;
            s += g_score_partial[row];
            c += g_count_partial[row];
        }
        const int   seq  = n_tokens / BSZ;
        const float mean = s / (float)seq;
        const float ce   = (float)c * ((float)EXPERTS / (float)(seq * TOPK));
        sm.ep.red[tid] = ce * mean;
        __syncthreads();
        for (int st = 128; st > 0; st >>= 1) {
            if (tid < st) sm.ep.red[tid] += sm.ep.red[tid + st];
            __syncthreads();
        }
        if (tid == 0) {
            out[(size_t)n_tokens * 2 * TOPK] = sm.ep.red[0] * (0.1f / (float)BSZ);
            g_arrive = 0;   // reset for next graph replay
        }
    }
}

// ---------------------------------------------------------------------------
extern "C" void kernel_launch(void* const* d_in, const int* in_sizes, int n_in,
                              void* d_out, int out_size)
{
    const float* X = (const float*)d_in[0];
    const float* W = (const float*)d_in[1];
    float* out = (float*)d_out;

    const int n_tokens = in_sizes[0] / DIM;   // 32768
    const int n_cta    = n_tokens / MT;       // 256

    mg_f32x2<<<n_cta, NTHREADS>>>(X, W, out, n_tokens);
}